// round 1
// baseline (speedup 1.0000x reference)
#include <cuda_runtime.h>
#include <math.h>

// Problem constants (fixed shapes)
#define D_DIM 4096
#define B_DIM 4
#define S_DIM 2048
#define K_EXP 8
#define R_DIM 16
#define KR    128               // K_EXP * R_DIM
#define T_TOK (B_DIM * S_DIM)   // 8192 tokens
#define SCALE 2.0f

// Scratch (device globals; no runtime allocation allowed)
__device__ __align__(16) float g_partial[B_DIM * 8 * D_DIM];   // per-(b,chunk) column sums
__device__ __align__(16) float g_weights[B_DIM * K_EXP];       // softmax router weights
__device__ __align__(16) float g_Bw[B_DIM * D_DIM * KR];       // 2*w[b,k]*lora_B[k,o,r]  (8 MB)
__device__ __align__(16) float g_h[T_TOK * KR];                // x @ A_cat^T             (4 MB)

// ---------------------------------------------------------------------------
// 1) Column sums of x over S-chunks of 256 rows: g_partial[(b*8+c)*D + d]
// ---------------------------------------------------------------------------
__global__ void mean_partial_kernel(const float* __restrict__ x) {
    int d = blockIdx.x * 256 + threadIdx.x;
    int b = blockIdx.y;
    int c = blockIdx.z;
    const float* p = x + ((size_t)(b * S_DIM + c * 256)) * D_DIM + d;
    float s = 0.f;
#pragma unroll 8
    for (int i = 0; i < 256; i++) s += p[(size_t)i * D_DIM];
    g_partial[(b * 8 + c) * D_DIM + d] = s;
}

// ---------------------------------------------------------------------------
// 2) Router: logits[b,k] = mean(x[b]) . router_w[k] + router_b[k]; softmax -> g_weights
// ---------------------------------------------------------------------------
__global__ void router_kernel(const float* __restrict__ rw, const float* __restrict__ rb) {
    int b = blockIdx.x;
    int tid = threadIdx.x;
    float acc[K_EXP];
#pragma unroll
    for (int k = 0; k < K_EXP; k++) acc[k] = 0.f;

    for (int d = tid; d < D_DIM; d += 256) {
        float m = 0.f;
#pragma unroll
        for (int c = 0; c < 8; c++) m += g_partial[(b * 8 + c) * D_DIM + d];
        m *= (1.0f / (float)S_DIM);
#pragma unroll
        for (int k = 0; k < K_EXP; k++) acc[k] += m * rw[k * D_DIM + d];
    }

    __shared__ float red[K_EXP][256];
#pragma unroll
    for (int k = 0; k < K_EXP; k++) red[k][tid] = acc[k];
    __syncthreads();

    if (tid < K_EXP) {
        float s = 0.f;
        for (int i = 0; i < 256; i++) s += red[tid][i];
        red[tid][0] = s + rb[tid];
    }
    __syncthreads();

    if (tid == 0) {
        float mx = -1e30f;
#pragma unroll
        for (int k = 0; k < K_EXP; k++) mx = fmaxf(mx, red[k][0]);
        float e[K_EXP], sum = 0.f;
#pragma unroll
        for (int k = 0; k < K_EXP; k++) { e[k] = expf(red[k][0] - mx); sum += e[k]; }
        float inv = 1.0f / sum;
#pragma unroll
        for (int k = 0; k < K_EXP; k++) g_weights[b * K_EXP + k] = e[k] * inv;
    }
}

// ---------------------------------------------------------------------------
// 3) Bw[b][o][k*16+r] = SCALE * w[b,k] * lora_B[k,o,r]
// ---------------------------------------------------------------------------
__global__ void bw_kernel(const float* __restrict__ loraB) {
    int idx = blockIdx.x * 256 + threadIdx.x;          // < 4*4096*128 = 2^21
    int b   = idx >> 19;                               // D_DIM*KR = 2^19
    int rem = idx & ((1 << 19) - 1);
    int o   = rem >> 7;
    int c   = rem & 127;
    int k   = c >> 4;
    int r   = c & 15;
    g_Bw[idx] = SCALE * g_weights[b * K_EXP + k] * loraB[(k * D_DIM + o) * R_DIM + r];
}

// ---------------------------------------------------------------------------
// 4) h[t][c] = sum_d x[t,d] * lora_A_flat[c,d]     (lora_A[K,R,D] flat == A_cat[128,4096])
//    Tiled GEMM: BM=64, BN=128 (all cols), BK=8, 256 threads, 4x8 microtile.
// ---------------------------------------------------------------------------
__global__ __launch_bounds__(256, 2) void h_gemm_kernel(const float* __restrict__ x,
                                                        const float* __restrict__ loraA) {
    __shared__ float As[8][64];
    __shared__ float Bs[8][128];
    int i0  = blockIdx.x * 64;
    int tid = threadIdx.x;
    int m0  = (tid >> 4) * 4;      // 0..60
    int n0  = (tid & 15) * 8;      // 0..120

    float acc[4][8];
#pragma unroll
    for (int mi = 0; mi < 4; mi++)
#pragma unroll
        for (int ni = 0; ni < 8; ni++) acc[mi][ni] = 0.f;

    int arow = tid >> 2, aq = (tid & 3) * 2;   // 64 rows x 8 k, 2 floats/thread
    int brow = tid >> 1, bq = (tid & 1) * 4;   // 128 rows x 8 k, 4 floats/thread
    const float* Ap = x     + (size_t)(i0 + arow) * D_DIM + aq;
    const float* Bp = loraA + (size_t)brow * D_DIM + bq;

    float2 av = *(const float2*)Ap;
    float4 bv = *(const float4*)Bp;

    for (int k0 = 0; k0 < D_DIM; k0 += 8) {
        As[aq + 0][arow] = av.x;  As[aq + 1][arow] = av.y;
        Bs[bq + 0][brow] = bv.x;  Bs[bq + 1][brow] = bv.y;
        Bs[bq + 2][brow] = bv.z;  Bs[bq + 3][brow] = bv.w;
        __syncthreads();
        if (k0 + 8 < D_DIM) {
            av = *(const float2*)(Ap + k0 + 8);
            bv = *(const float4*)(Bp + k0 + 8);
        }
#pragma unroll
        for (int kk = 0; kk < 8; kk++) {
            float4 a4 = *(const float4*)&As[kk][m0];
            float4 b0 = *(const float4*)&Bs[kk][n0];
            float4 b1 = *(const float4*)&Bs[kk][n0 + 4];
            float a[4]  = {a4.x, a4.y, a4.z, a4.w};
            float bb[8] = {b0.x, b0.y, b0.z, b0.w, b1.x, b1.y, b1.z, b1.w};
#pragma unroll
            for (int mi = 0; mi < 4; mi++)
#pragma unroll
                for (int ni = 0; ni < 8; ni++)
                    acc[mi][ni] = fmaf(a[mi], bb[ni], acc[mi][ni]);
        }
        __syncthreads();
    }

#pragma unroll
    for (int mi = 0; mi < 4; mi++) {
        float4 v0 = {acc[mi][0], acc[mi][1], acc[mi][2], acc[mi][3]};
        float4 v1 = {acc[mi][4], acc[mi][5], acc[mi][6], acc[mi][7]};
        size_t base = (size_t)(i0 + m0 + mi) * KR + n0;
        *(float4*)&g_h[base]     = v0;
        *(float4*)&g_h[base + 4] = v1;
    }
}

// ---------------------------------------------------------------------------
// 5) Main fused GEMM: out[t,o] = sum_d x[t,d]W[o,d] + sum_c h[t,c]Bw[b][o,c] + bias[o]
//    Phase 0: K=4096 over (x, W). Phase 1: K=128 over (g_h, g_Bw[b]).
//    BM=BN=128, BK=8, 256 threads, 8x8 microtile.
// ---------------------------------------------------------------------------
__global__ __launch_bounds__(256, 2) void main_gemm_kernel(const float* __restrict__ x,
                                                           const float* __restrict__ W,
                                                           const float* __restrict__ bias,
                                                           float* __restrict__ out) {
    __shared__ float As[8][128];
    __shared__ float Bs[8][128];
    int j0  = blockIdx.x * 128;     // output column tile
    int i0  = blockIdx.y * 128;     // token tile
    int b   = i0 >> 11;             // i0 / 2048: batch of this token tile
    int tid = threadIdx.x;
    int m0  = (tid >> 4) * 8;
    int n0  = (tid & 15) * 8;
    int lrow = tid >> 1, lq = (tid & 1) * 4;   // 128 rows x 8 k, float4/thread

    float acc[8][8];
#pragma unroll
    for (int mi = 0; mi < 8; mi++)
#pragma unroll
        for (int ni = 0; ni < 8; ni++) acc[mi][ni] = 0.f;

#pragma unroll 1
    for (int phase = 0; phase < 2; phase++) {
        const float* Ap;
        const float* Bp;
        int Kp;
        if (phase == 0) {
            Ap = x + (size_t)(i0 + lrow) * D_DIM + lq;
            Bp = W + (size_t)(j0 + lrow) * D_DIM + lq;
            Kp = D_DIM;
        } else {
            Ap = g_h  + (size_t)(i0 + lrow) * KR + lq;
            Bp = g_Bw + ((size_t)b * D_DIM + (size_t)(j0 + lrow)) * KR + lq;
            Kp = KR;
        }
        float4 av = *(const float4*)Ap;
        float4 bv = *(const float4*)Bp;

        for (int k0 = 0; k0 < Kp; k0 += 8) {
            As[lq + 0][lrow] = av.x;  As[lq + 1][lrow] = av.y;
            As[lq + 2][lrow] = av.z;  As[lq + 3][lrow] = av.w;
            Bs[lq + 0][lrow] = bv.x;  Bs[lq + 1][lrow] = bv.y;
            Bs[lq + 2][lrow] = bv.z;  Bs[lq + 3][lrow] = bv.w;
            __syncthreads();
            if (k0 + 8 < Kp) {
                av = *(const float4*)(Ap + k0 + 8);
                bv = *(const float4*)(Bp + k0 + 8);
            }
#pragma unroll
            for (int kk = 0; kk < 8; kk++) {
                float4 a0 = *(const float4*)&As[kk][m0];
                float4 a1 = *(const float4*)&As[kk][m0 + 4];
                float4 b0 = *(const float4*)&Bs[kk][n0];
                float4 b1 = *(const float4*)&Bs[kk][n0 + 4];
                float a[8]  = {a0.x, a0.y, a0.z, a0.w, a1.x, a1.y, a1.z, a1.w};
                float bb[8] = {b0.x, b0.y, b0.z, b0.w, b1.x, b1.y, b1.z, b1.w};
#pragma unroll
                for (int mi = 0; mi < 8; mi++)
#pragma unroll
                    for (int ni = 0; ni < 8; ni++)
                        acc[mi][ni] = fmaf(a[mi], bb[ni], acc[mi][ni]);
            }
            __syncthreads();
        }
    }

    // Epilogue: add bias, write out
    float bb0[8];
#pragma unroll
    for (int ni = 0; ni < 8; ni++) bb0[ni] = bias[j0 + n0 + ni];

#pragma unroll
    for (int mi = 0; mi < 8; mi++) {
        size_t base = (size_t)(i0 + m0 + mi) * D_DIM + j0 + n0;
        float4 v0 = {acc[mi][0] + bb0[0], acc[mi][1] + bb0[1],
                     acc[mi][2] + bb0[2], acc[mi][3] + bb0[3]};
        float4 v1 = {acc[mi][4] + bb0[4], acc[mi][5] + bb0[5],
                     acc[mi][6] + bb0[6], acc[mi][7] + bb0[7]};
        *(float4*)&out[base]     = v0;
        *(float4*)&out[base + 4] = v1;
    }
}

// ---------------------------------------------------------------------------
extern "C" void kernel_launch(void* const* d_in, const int* in_sizes, int n_in,
                              void* d_out, int out_size) {
    const float* x      = (const float*)d_in[0];   // [4,2048,4096]
    const float* base_w = (const float*)d_in[1];   // [4096,4096]
    const float* base_b = (const float*)d_in[2];   // [4096]
    const float* lora_A = (const float*)d_in[3];   // [8,16,4096]
    const float* lora_B = (const float*)d_in[4];   // [8,4096,16]
    const float* rout_w = (const float*)d_in[5];   // [8,4096]
    const float* rout_b = (const float*)d_in[6];   // [8]
    float* out = (float*)d_out;

    // 1) column partial sums for mean pooling
    mean_partial_kernel<<<dim3(D_DIM / 256, B_DIM, 8), 256>>>(x);
    // 2) router softmax weights
    router_kernel<<<B_DIM, 256>>>(rout_w, rout_b);
    // 3) weighted/concatenated lora_B
    bw_kernel<<<(B_DIM * D_DIM * KR) / 256, 256>>>(lora_B);
    // 4) h = x @ A_cat^T
    h_gemm_kernel<<<T_TOK / 64, 256>>>(x, lora_A);
    // 5) fused base GEMM + LoRA extension + bias
    main_gemm_kernel<<<dim3(D_DIM / 128, T_TOK / 128), 256>>>(x, base_w, base_b, out);
}

// round 3
// speedup vs baseline: 6.1816x; 6.1816x over previous
#include <cuda_runtime.h>
#include <cuda_fp16.h>
#include <cstdint>
#include <math.h>

// ---------------- Problem constants ----------------
#define D_DIM 4096
#define S_DIM 2048
#define B_DIM 4
#define K_EXP 8
#define R_DIM 16
#define KR    128
#define T_TOK 8192
#define SCALE 2.0f

// ---------------- Device scratch (static; no runtime alloc) ----------------
__device__ __align__(16) float  g_partial[B_DIM * 8 * D_DIM];
__device__ float  g_weights[B_DIM * K_EXP];
__device__ __align__(16) __half g_xh[(size_t)T_TOK * D_DIM];          // 64 MB
__device__ __align__(16) __half g_wh[(size_t)D_DIM * D_DIM];          // 32 MB
__device__ __align__(16) __half g_ah[(size_t)KR * D_DIM];             //  1 MB
__device__ __align__(16) __half g_Bwh[(size_t)B_DIM * D_DIM * KR];    //  4 MB
__device__ __align__(16) __half g_hh[(size_t)T_TOK * KR];             //  2 MB

// ---------------- PTX helpers ----------------
__device__ __forceinline__ uint32_t smem_u32(const void* p) {
    uint32_t a;
    asm("{ .reg .u64 t; cvta.to.shared.u64 t, %1; cvt.u32.u64 %0, t; }"
        : "=r"(a) : "l"(p));
    return a;
}

#define CP_ASYNC16(dst, src) \
    asm volatile("cp.async.cg.shared.global [%0], [%1], 16;" \
                 :: "r"(dst), "l"(src) : "memory")
#define CP_COMMIT() asm volatile("cp.async.commit_group;" ::: "memory")
#define CP_WAIT(n)  asm volatile("cp.async.wait_group %0;" :: "n"(n) : "memory")

#define LDSM4(r0, r1, r2, r3, addr) \
    asm volatile("ldmatrix.sync.aligned.m8n8.x4.shared.b16 {%0,%1,%2,%3}, [%4];" \
                 : "=r"(r0), "=r"(r1), "=r"(r2), "=r"(r3) : "r"(addr))

#define MMA16816(d, a, b) \
    asm volatile("mma.sync.aligned.m16n8k16.row.col.f32.f16.f16.f32 " \
                 "{%0,%1,%2,%3},{%4,%5,%6,%7},{%8,%9},{%0,%1,%2,%3};" \
                 : "+f"((d)[0]), "+f"((d)[1]), "+f"((d)[2]), "+f"((d)[3]) \
                 : "r"((a)[0]), "r"((a)[1]), "r"((a)[2]), "r"((a)[3]), \
                   "r"((b)[0]), "r"((b)[1]))

// Swizzled smem address: tile rows of 32 halfs (64 B), 4 16-byte chunks/row,
// chunk' = chunk ^ ((row>>1)&3) -> conflict-free ldmatrix + cp.async.
__device__ __forceinline__ uint32_t sw_addr(uint32_t base, int row, int ch) {
    return base + row * 64 + ((uint32_t)(ch ^ ((row >> 1) & 3)) << 4);
}

// ---------------------------------------------------------------------------
// Aux kernels
// ---------------------------------------------------------------------------
__global__ void cvt_f2h_kernel(const float* __restrict__ s, __half* __restrict__ d) {
    size_t i = ((size_t)blockIdx.x * 256 + threadIdx.x) * 4;
    float4 v = *(const float4*)(s + i);
    __half2 h0 = __floats2half2_rn(v.x, v.y);
    __half2 h1 = __floats2half2_rn(v.z, v.w);
    *(__half2*)(d + i)     = h0;
    *(__half2*)(d + i + 2) = h1;
}

__global__ void mean_partial_kernel(const float* __restrict__ x) {
    int d = blockIdx.x * 256 + threadIdx.x;
    int b = blockIdx.y;
    int c = blockIdx.z;
    const float* p = x + ((size_t)(b * S_DIM + c * 256)) * D_DIM + d;
    float s = 0.f;
#pragma unroll 8
    for (int i = 0; i < 256; i++) s += p[(size_t)i * D_DIM];
    g_partial[(b * 8 + c) * D_DIM + d] = s;
}

__global__ void router_kernel(const float* __restrict__ rw, const float* __restrict__ rb) {
    int b = blockIdx.x;
    int tid = threadIdx.x;
    float acc[K_EXP];
#pragma unroll
    for (int k = 0; k < K_EXP; k++) acc[k] = 0.f;

    for (int d = tid; d < D_DIM; d += 256) {
        float m = 0.f;
#pragma unroll
        for (int c = 0; c < 8; c++) m += g_partial[(b * 8 + c) * D_DIM + d];
        m *= (1.0f / (float)S_DIM);
#pragma unroll
        for (int k = 0; k < K_EXP; k++) acc[k] += m * rw[k * D_DIM + d];
    }

    __shared__ float red[K_EXP][256];
#pragma unroll
    for (int k = 0; k < K_EXP; k++) red[k][tid] = acc[k];
    __syncthreads();

    if (tid < K_EXP) {
        float s = 0.f;
        for (int i = 0; i < 256; i++) s += red[tid][i];
        red[tid][0] = s + rb[tid];
    }
    __syncthreads();

    if (tid == 0) {
        float mx = -1e30f;
#pragma unroll
        for (int k = 0; k < K_EXP; k++) mx = fmaxf(mx, red[k][0]);
        float e[K_EXP], sum = 0.f;
#pragma unroll
        for (int k = 0; k < K_EXP; k++) { e[k] = expf(red[k][0] - mx); sum += e[k]; }
        float inv = 1.0f / sum;
#pragma unroll
        for (int k = 0; k < K_EXP; k++) g_weights[b * K_EXP + k] = e[k] * inv;
    }
}

__global__ void bw_kernel(const float* __restrict__ loraB) {
    int idx = blockIdx.x * 256 + threadIdx.x;           // < 2^21
    int b   = idx >> 19;
    int rem = idx & ((1 << 19) - 1);
    int o   = rem >> 7;
    int c   = rem & 127;
    int k   = c >> 4;
    int r   = c & 15;
    float v = SCALE * g_weights[b * K_EXP + k] * loraB[(k * D_DIM + o) * R_DIM + r];
    g_Bwh[idx] = __float2half_rn(v);
}

// ---------------------------------------------------------------------------
// Pipelined fp16 mma.sync GEMM.
//   C[i,j] = sum_k A[i,k]*Bm[j,k]  (+ EXT: sum_c A2[i,c]*B2[b(i),j,c]) (+ bias[j])
// BM=BN=128, BK=32, 4-stage cp.async, 8 warps (2 M x 4 N), 64x32 warp tiles.
// ---------------------------------------------------------------------------
template <bool EXT, bool BIAS, bool OUTH>
__global__ void __launch_bounds__(256, 2) mma_gemm_kernel(
    const __half* __restrict__ A, int lda,
    const __half* __restrict__ Bm, int ldb,
    const __half* __restrict__ A2,
    const __half* __restrict__ B2all,
    const float* __restrict__ bias,
    float* __restrict__ outf, __half* __restrict__ outh,
    int ldc, int iters0, int iters)
{
    extern __shared__ __align__(128) char smem[];
    const uint32_t sbase = smem_u32(smem);
    const int tid  = threadIdx.x;
    const int lane = tid & 31;
    const int wid  = tid >> 5;
    const int wm   = wid & 1;       // 2 warps over M
    const int wn   = wid >> 1;      // 4 warps over N
    const int i0   = blockIdx.y * 128;
    const int j0   = blockIdx.x * 128;
    const __half* B2 = nullptr;
    if (EXT) B2 = B2all + (size_t)(i0 >> 11) * ((size_t)D_DIM * KR);

    // cooperative stage loader: 512 A-chunks + 512 B-chunks of 16 B
    auto loadst = [&](int git, int st) {
        uint32_t abase = sbase + st * 16384;
        uint32_t bbase = abase + 8192;
#pragma unroll
        for (int t = 0; t < 2; t++) {
            int idx = tid + t * 256;
            int row = idx >> 2, ch = idx & 3;
            const __half* src;
            if (!EXT || git < iters0)
                src = A + (size_t)(i0 + row) * lda + git * 32 + ch * 8;
            else
                src = A2 + (size_t)(i0 + row) * KR + (git - iters0) * 32 + ch * 8;
            CP_ASYNC16(sw_addr(abase, row, ch), src);
        }
#pragma unroll
        for (int t = 0; t < 2; t++) {
            int idx = tid + t * 256;
            int row = idx >> 2, ch = idx & 3;
            const __half* src;
            if (!EXT || git < iters0)
                src = Bm + (size_t)(j0 + row) * ldb + git * 32 + ch * 8;
            else
                src = B2 + (size_t)(j0 + row) * KR + (git - iters0) * 32 + ch * 8;
            CP_ASYNC16(sw_addr(bbase, row, ch), src);
        }
    };

    float acc[4][4][4];
#pragma unroll
    for (int mi = 0; mi < 4; mi++)
#pragma unroll
        for (int ni = 0; ni < 4; ni++)
#pragma unroll
            for (int e = 0; e < 4; e++) acc[mi][ni][e] = 0.f;

    // prologue: 3 stages in flight
#pragma unroll
    for (int s = 0; s < 3; s++) { loadst(s, s); CP_COMMIT(); }

    for (int it = 0; it < iters; ++it) {
        CP_WAIT(2);
        __syncthreads();
        if (it + 3 < iters) loadst(it + 3, (it + 3) & 3);
        CP_COMMIT();

        uint32_t sA = sbase + (it & 3) * 16384;
        uint32_t sB = sA + 8192;
#pragma unroll
        for (int ks = 0; ks < 2; ks++) {
            int ch = ks * 2 + (lane >> 4);
            uint32_t a[4][4];
#pragma unroll
            for (int mi = 0; mi < 4; mi++) {
                int row = wm * 64 + mi * 16 + (lane & 15);
                LDSM4(a[mi][0], a[mi][1], a[mi][2], a[mi][3], sw_addr(sA, row, ch));
            }
            uint32_t b[4][2];
#pragma unroll
            for (int j = 0; j < 2; j++) {
                int row = wn * 32 + j * 16 + (lane & 15);
                uint32_t t0, t1, t2, t3;
                LDSM4(t0, t1, t2, t3, sw_addr(sB, row, ch));
                b[2 * j][0]     = t0; b[2 * j][1]     = t2;
                b[2 * j + 1][0] = t1; b[2 * j + 1][1] = t3;
            }
#pragma unroll
            for (int mi = 0; mi < 4; mi++)
#pragma unroll
                for (int ni = 0; ni < 4; ni++)
                    MMA16816(acc[mi][ni], a[mi], b[ni]);
        }
    }

    // epilogue
#pragma unroll
    for (int mi = 0; mi < 4; mi++) {
        int r0 = i0 + wm * 64 + mi * 16 + (lane >> 2);
#pragma unroll
        for (int ni = 0; ni < 4; ni++) {
            int c0 = j0 + wn * 32 + ni * 8 + 2 * (lane & 3);
            if (OUTH) {
                __half2 h0 = __floats2half2_rn(acc[mi][ni][0], acc[mi][ni][1]);
                __half2 h1 = __floats2half2_rn(acc[mi][ni][2], acc[mi][ni][3]);
                *(__half2*)(outh + (size_t)r0 * ldc + c0)       = h0;
                *(__half2*)(outh + (size_t)(r0 + 8) * ldc + c0) = h1;
            } else {
                float b0 = 0.f, b1 = 0.f;
                if (BIAS) { b0 = bias[c0]; b1 = bias[c0 + 1]; }
                float2 v0 = { acc[mi][ni][0] + b0, acc[mi][ni][1] + b1 };
                float2 v1 = { acc[mi][ni][2] + b0, acc[mi][ni][3] + b1 };
                *(float2*)(outf + (size_t)r0 * ldc + c0)       = v0;
                *(float2*)(outf + (size_t)(r0 + 8) * ldc + c0) = v1;
            }
        }
    }
}

// ---------------------------------------------------------------------------
extern "C" void kernel_launch(void* const* d_in, const int* in_sizes, int n_in,
                              void* d_out, int out_size) {
    const float* x      = (const float*)d_in[0];   // [4,2048,4096]
    const float* base_w = (const float*)d_in[1];   // [4096,4096]
    const float* base_b = (const float*)d_in[2];   // [4096]
    const float* lora_A = (const float*)d_in[3];   // [8,16,4096]
    const float* lora_B = (const float*)d_in[4];   // [8,4096,16]
    const float* rout_w = (const float*)d_in[5];   // [8,4096]
    const float* rout_b = (const float*)d_in[6];   // [8]
    float* out = (float*)d_out;

    const int SMEM = 4 * 16384;   // 64 KB dynamic
    cudaFuncSetAttribute(mma_gemm_kernel<true, true, false>,
                         cudaFuncAttributeMaxDynamicSharedMemorySize, SMEM);
    cudaFuncSetAttribute(mma_gemm_kernel<false, false, true>,
                         cudaFuncAttributeMaxDynamicSharedMemorySize, SMEM);

    __half* xh;  cudaGetSymbolAddress((void**)&xh,  g_xh);
    __half* wh;  cudaGetSymbolAddress((void**)&wh,  g_wh);
    __half* ah;  cudaGetSymbolAddress((void**)&ah,  g_ah);
    __half* bwh; cudaGetSymbolAddress((void**)&bwh, g_Bwh);
    __half* hh;  cudaGetSymbolAddress((void**)&hh,  g_hh);

    // fp32 -> fp16 conversions
    cvt_f2h_kernel<<<(T_TOK * (size_t)D_DIM) / 1024, 256>>>(x, xh);
    cvt_f2h_kernel<<<((size_t)D_DIM * D_DIM) / 1024, 256>>>(base_w, wh);
    cvt_f2h_kernel<<<((size_t)KR * D_DIM) / 1024, 256>>>(lora_A, ah);

    // router path (fp32)
    mean_partial_kernel<<<dim3(D_DIM / 256, B_DIM, 8), 256>>>(x);
    router_kernel<<<B_DIM, 256>>>(rout_w, rout_b);
    bw_kernel<<<(B_DIM * D_DIM * KR) / 256, 256>>>(lora_B);

    // h = x @ A_cat^T  (M=8192, N=128, K=4096) -> g_hh (fp16)
    mma_gemm_kernel<false, false, true><<<dim3(1, T_TOK / 128), 256, SMEM>>>(
        xh, D_DIM, ah, D_DIM, nullptr, nullptr, nullptr,
        nullptr, hh, KR, 128, 128);

    // out = x @ W^T + h @ Bw^T + bias  (K = 4096 + 128)
    mma_gemm_kernel<true, true, false><<<dim3(D_DIM / 128, T_TOK / 128), 256, SMEM>>>(
        xh, D_DIM, wh, D_DIM, hh, bwh, base_b,
        out, nullptr, D_DIM, 128, 132);
}